// round 13
// baseline (speedup 1.0000x reference)
#include <cuda_runtime.h>
#include <math.h>

#define T_TREES 128
#define B_BATCH 1024
#define D_FEAT  784
#define K_TOP   200
#define D4      (D_FEAT / 4)   // 196
#define D8      (D_FEAT / 8)   // 98

#define BT 4            // batch rows per tile
#define TT 4            // tree rows per tile
#define NJ 2            // ceil(BT*D8 / 256) = ceil(392/256)
#define NTILES ((B_BATCH / BT) * (T_TREES / TT))   // 4096
#define NTAIL  (T_TREES / TT)                      // 32 attn-copy blocks

#define NSLOT 25   // ceil(784/32)

// Selected attention matrix [T, D], float4-aligned (kernel hand-off).
__device__ float4 g_attn4[T_TREES * D4];

// ---------------------------------------------------------------------------
// Kernel 1: per-tree top-K selection, ONE WARP PER TREE. Writes ONLY g_attn.
// Exact K-th key via binary search on the uint bits of sigmoid(m) (s>0 ->
// monotone key); ties broken lowest-index-first (jax.lax.top_k semantics).
// ---------------------------------------------------------------------------
__global__ __launch_bounds__(32) void attn_select_kernel(
    const float* __restrict__ mask)
{
    const int t    = blockIdx.x;
    const int lane = threadIdx.x;
    const float* row = mask + t * D_FEAT;

    unsigned keys[NSLOT];
    #pragma unroll
    for (int i = 0; i < NSLOT; i++) {
        int d = i * 32 + lane;
        if (d < D_FEAT) {
            float m = row[d];
            float s = 1.0f / (1.0f + expf(-m));
            keys[i] = __float_as_uint(s);   // s in (0,1): monotone uint key
        } else {
            keys[i] = 0u;
        }
    }

    // K-th largest key: max lo with count(key >= lo) >= K.
    // mask ~ U[-1,1) -> s in (0.2689, 0.7311); bracket with slack.
    unsigned lo = 0x3E800000u, hi = 0x3F3C0000u;
    while (lo < hi) {
        unsigned mid = lo + ((hi - lo + 1u) >> 1);
        int c = 0;
        #pragma unroll
        for (int i = 0; i < NSLOT; i++) c += (keys[i] >= mid);
        c = __reduce_add_sync(0xFFFFFFFFu, c);
        if (c >= K_TOP) lo = mid; else hi = mid - 1u;
    }

    int cg = 0;
    #pragma unroll
    for (int i = 0; i < NSLOT; i++) cg += (keys[i] > lo);
    cg = __reduce_add_sync(0xFFFFFFFFu, cg);
    const int need = K_TOP - cg;

    float* g_attn = (float*)g_attn4;
    const unsigned below = (1u << lane) - 1u;
    int running = 0;
    #pragma unroll
    for (int i = 0; i < NSLOT; i++) {
        int d = i * 32 + lane;
        bool tie = (keys[i] == lo) && (d < D_FEAT);
        unsigned bm = __ballot_sync(0xFFFFFFFFu, tie);
        int rank = running + __popc(bm & below);
        bool keep = (keys[i] > lo) || (tie && rank < need);
        running += __popc(bm);
        if (d < D_FEAT)
            g_attn[t * D_FEAT + d] = keep ? __uint_as_float(keys[i]) : 0.0f;
    }
}

// 256-bit streaming store (sm_100+). Output is never re-read.
__device__ __forceinline__ void stg256_cs(float4* p, float4 a, float4 b)
{
    asm volatile(
        "st.global.cs.v8.f32 [%0], {%1,%2,%3,%4,%5,%6,%7,%8};"
        :: "l"(p),
           "f"(a.x), "f"(a.y), "f"(a.z), "f"(a.w),
           "f"(b.x), "f"(b.y), "f"(b.z), "f"(b.w)
        : "memory");
}

// ---------------------------------------------------------------------------
// Kernel 2: out[b,t,d] = x[b,d] * attn[t,d]. BT=4/TT=4 tile (measured best),
// 256-bit stores: each thread owns a float8 (two adjacent float4s), halving
// L1 store wavefronts (L1 was 71.6% busy with STG.128 — co-limiting with
// DRAM). Every (b,t) output row is 3136 B = 98 x 32 B, so all v8 stores are
// 32B-aligned. First NTAIL blocks emit the attention output copy.
// ---------------------------------------------------------------------------
__global__ __launch_bounds__(256) void bcast_mul_kernel(
    const float4* __restrict__ x4, float4* __restrict__ o4,
    float4* __restrict__ attn_tail4)
{
    __shared__ float4 sa[TT * D4];  // 12544 B

    const int tb  = blockIdx.x;
    const int tid = threadIdx.x;

    if (tb < NTAIL) {                // attention-output copy blocks (early)
        const int tt0 = tb * TT;
        for (int j = tid; j < TT * D4; j += 256)
            attn_tail4[tt0 * D4 + j] = g_attn4[tt0 * D4 + j];
        return;
    }

    const int tile = tb - NTAIL;
    const int t0 = (tile & 31) * TT;      // 128/TT = 32 t-tiles
    const int b0 = (tile >> 5) * BT;      // 1024/BT = 256 b-tiles

    // Prefetch this thread's x float8s (independent of the attn fill).
    float4 xlo[NJ], xhi[NJ];
    #pragma unroll
    for (int k = 0; k < NJ; k++) {
        int j = tid + k * 256;
        if (j < BT * D8) {
            int bl = j / D8;
            int d8 = j - bl * D8;
            const float4* p = x4 + (b0 + bl) * D4 + d8 * 2;
            xlo[k] = __ldg(p);
            xhi[k] = __ldg(p + 1);
        }
    }

    for (int j = tid; j < TT * D4; j += 256)
        sa[j] = g_attn4[t0 * D4 + j];     // rows t0..t0+3 contiguous
    __syncthreads();

    #pragma unroll
    for (int k = 0; k < NJ; k++) {
        int j = tid + k * 256;
        if (j >= BT * D8) break;
        const int bl = j / D8;
        const int d8 = j - bl * D8;
        const float4 vlo = xlo[k];
        const float4 vhi = xhi[k];
        const int base = ((b0 + bl) * T_TREES + t0) * D4 + d8 * 2;
        #pragma unroll
        for (int tl = 0; tl < TT; tl++) {
            float4 alo = sa[tl * D4 + d8 * 2];
            float4 ahi = sa[tl * D4 + d8 * 2 + 1];
            float4 rlo, rhi;
            rlo.x = vlo.x * alo.x;  rlo.y = vlo.y * alo.y;
            rlo.z = vlo.z * alo.z;  rlo.w = vlo.w * alo.w;
            rhi.x = vhi.x * ahi.x;  rhi.y = vhi.y * ahi.y;
            rhi.z = vhi.z * ahi.z;  rhi.w = vhi.w * ahi.w;
            stg256_cs(o4 + base + tl * D4, rlo, rhi);
        }
    }
}

extern "C" void kernel_launch(void* const* d_in, const int* in_sizes, int n_in,
                              void* d_out, int out_size)
{
    const float* x    = (const float*)d_in[0];
    const float* mask = (const float*)d_in[1];
    if (n_in >= 2 && in_sizes[0] == T_TREES * D_FEAT) {
        x    = (const float*)d_in[1];
        mask = (const float*)d_in[0];
    }

    float* out = (float*)d_out;
    float* attn_tail = out + (size_t)B_BATCH * T_TREES * D_FEAT;

    attn_select_kernel<<<T_TREES, 32>>>(mask);
    bcast_mul_kernel<<<NTILES + NTAIL, 256>>>(
        (const float4*)x, (float4*)out, (float4*)attn_tail);
}

// round 14
// speedup vs baseline: 1.1584x; 1.1584x over previous
#include <cuda_runtime.h>
#include <math.h>

#define T_TREES 128
#define B_BATCH 1024
#define D_FEAT  784
#define K_TOP   200
#define D4      (D_FEAT / 4)   // 196

#define BT 4            // batch rows per tile
#define TT 8            // tree rows per tile
#define NJ 4            // ceil(BT*D4 / 256) = ceil(784/256)
#define NTILES ((B_BATCH / BT) * (T_TREES / TT))   // 4096

#define NSLOT 25   // ceil(784/32)

// Selected attention matrix [T, D], float4-aligned (kernel hand-off).
__device__ float4 g_attn4[T_TREES * D4];

// ---------------------------------------------------------------------------
// Kernel 1: per-tree top-K selection, ONE WARP PER TREE. Exact K-th key via
// binary search on the uint bits of sigmoid(m) (s>0 -> monotone key); ties
// broken lowest-index-first (jax.lax.top_k semantics). Writes g_attn (for
// the broadcast kernel) and the attention output.
// ---------------------------------------------------------------------------
__global__ __launch_bounds__(32) void attn_select_kernel(
    const float* __restrict__ mask, float* __restrict__ attn_out)
{
    const int t    = blockIdx.x;
    const int lane = threadIdx.x;
    const float* row = mask + t * D_FEAT;

    unsigned keys[NSLOT];
    #pragma unroll
    for (int i = 0; i < NSLOT; i++) {
        int d = i * 32 + lane;
        if (d < D_FEAT) {
            float m = row[d];
            float s = 1.0f / (1.0f + expf(-m));
            keys[i] = __float_as_uint(s);   // s in (0,1): monotone uint key
        } else {
            keys[i] = 0u;
        }
    }

    // K-th largest key: max lo with count(key >= lo) >= K.
    // mask ~ U[-1,1) -> s in (0.2689, 0.7311); bracket with slack.
    unsigned lo = 0x3E800000u, hi = 0x3F3C0000u;
    while (lo < hi) {
        unsigned mid = lo + ((hi - lo + 1u) >> 1);
        int c = 0;
        #pragma unroll
        for (int i = 0; i < NSLOT; i++) c += (keys[i] >= mid);
        c = __reduce_add_sync(0xFFFFFFFFu, c);
        if (c >= K_TOP) lo = mid; else hi = mid - 1u;
    }

    int cg = 0;
    #pragma unroll
    for (int i = 0; i < NSLOT; i++) cg += (keys[i] > lo);
    cg = __reduce_add_sync(0xFFFFFFFFu, cg);
    const int need = K_TOP - cg;

    float* g_attn = (float*)g_attn4;
    const unsigned below = (1u << lane) - 1u;
    int running = 0;
    #pragma unroll
    for (int i = 0; i < NSLOT; i++) {
        int d = i * 32 + lane;
        bool tie = (keys[i] == lo) && (d < D_FEAT);
        unsigned bm = __ballot_sync(0xFFFFFFFFu, tie);
        int rank = running + __popc(bm & below);
        bool keep = (keys[i] > lo) || (tie && rank < need);
        running += __popc(bm);
        if (d < D_FEAT) {
            float outv = keep ? __uint_as_float(keys[i]) : 0.0f;
            g_attn[t * D_FEAT + d]   = outv;
            attn_out[t * D_FEAT + d] = outv;
        }
    }
}

// ---------------------------------------------------------------------------
// Kernel 2: out[b,t,d] = x[b,d] * attn[t,d]. BT=4 (measured-best register
// prefetch xv[4], regs=40, 6 blocks/SM) with TT=8: halves x's L2 re-read
// volume vs TT=4 at unchanged occupancy, 8 consecutive STG.128 per x
// register. attn tile staged in smem (4x reuse), streaming 128-bit stores
// (output never re-read).
// ---------------------------------------------------------------------------
__global__ __launch_bounds__(256) void bcast_mul_kernel(
    const float4* __restrict__ x4, float4* __restrict__ o4)
{
    __shared__ float4 sa[TT * D4];  // 25088 B

    const int tb  = blockIdx.x;
    const int tid = threadIdx.x;

    const int t0 = (tb & 15) * TT;        // 128/TT = 16 t-tiles
    const int b0 = (tb >> 4) * BT;        // 1024/BT = 256 b-tiles

    // Prefetch this thread's x elements (independent of the attn fill).
    float4 xv[NJ];
    #pragma unroll
    for (int k = 0; k < NJ; k++) {
        int j = tid + k * 256;
        if (j < BT * D4) xv[k] = __ldg(&x4[b0 * D4 + j]);  // (b0+bl)*D4+d4
    }

    for (int j = tid; j < TT * D4; j += 256)
        sa[j] = g_attn4[t0 * D4 + j];     // rows t0..t0+7 contiguous
    __syncthreads();

    #pragma unroll
    for (int k = 0; k < NJ; k++) {
        int j = tid + k * 256;
        if (j >= BT * D4) break;
        const int bl = j / D4;
        const int d4 = j - bl * D4;
        const float4 v = xv[k];
        const int base = ((b0 + bl) * T_TREES + t0) * D4 + d4;
        #pragma unroll
        for (int tl = 0; tl < TT; tl++) {
            float4 av = sa[tl * D4 + d4];
            float4 r;
            r.x = v.x * av.x;
            r.y = v.y * av.y;
            r.z = v.z * av.z;
            r.w = v.w * av.w;
            __stcs(&o4[base + tl * D4], r);
        }
    }
}

extern "C" void kernel_launch(void* const* d_in, const int* in_sizes, int n_in,
                              void* d_out, int out_size)
{
    const float* x    = (const float*)d_in[0];
    const float* mask = (const float*)d_in[1];
    if (n_in >= 2 && in_sizes[0] == T_TREES * D_FEAT) {
        x    = (const float*)d_in[1];
        mask = (const float*)d_in[0];
    }

    float* out = (float*)d_out;
    float* attn_tail = out + (size_t)B_BATCH * T_TREES * D_FEAT;

    attn_select_kernel<<<T_TREES, 32>>>(mask, attn_tail);
    bcast_mul_kernel<<<NTILES, 256>>>((const float4*)x, (float4*)out);
}